// round 9
// baseline (speedup 1.0000x reference)
#include <cuda_runtime.h>
#include <cuda_bf16.h>
#include <cstdint>

// Problem dims (fixed by the dataset)
#define T_STEPS 128
#define BATCH   128
#define D_IN    1024
#define D_OUT   1024
#define M_TOT   (T_STEPS * BATCH)   // 16384
#define BD      (BATCH * D_OUT)     // 131072

// GEMM tiling: 128x128 CTA tile, 512 threads, 4x(4x2) per thread
#define BM 128
#define BN 128
#define BK 16
#define TM 4
#define NTHREADS 512
#define NITER   (D_IN / BK)     // 64
#define FOLD_IT 32              // iteration where K=512 chunk boundary falls

// Scratch for X = A @ W + b  (64 MB) — __device__ global, no allocation.
__device__ float g_X[(size_t)M_TOT * D_OUT];

typedef unsigned long long ull;

// Packed f32x2: two independent IEEE-rn fp32 ops per instruction.
// Per-lane results are bit-identical to scalar FFMA / FADD.rn.
__device__ __forceinline__ ull fma2(ull a, ull b, ull c) {
    ull d;
    asm("fma.rn.f32x2 %0, %1, %2, %3;" : "=l"(d) : "l"(a), "l"(b), "l"(c));
    return d;
}
__device__ __forceinline__ ull add2(ull a, ull b) {
    ull d;
    asm("add.rn.f32x2 %0, %1, %2;" : "=l"(d) : "l"(a), "l"(b));
    return d;
}
__device__ __forceinline__ float2 unpack2(ull v) {
    float2 f;
    asm("mov.b64 {%0, %1}, %2;" : "=f"(f.x), "=f"(f.y) : "l"(v));
    return f;
}

// ---------------------------------------------------------------------------
// Kernel 1: X[16384,1024] = A[16384,1024] @ W[1024,1024] + b
// Bit-exact split-K=2 ordering (PROVEN: rel_err == 0.0):
//   c0 = serial ascending FFMA over k=0..511
//   c1 = serial ascending FFMA over k=512..1023
//   X  = ((c0 + c1) + bias), each add separately rounded.
// 512 threads / 16 warps per CTA (4 warps/SMSP) to keep the FFMA2 pipe
// (rt=3, register-bank-bound) saturated across LDS/global latencies.
// ---------------------------------------------------------------------------
__global__ __launch_bounds__(NTHREADS, 1)
void sgemm_bias_splitk2_f32x2_kernel(const float* __restrict__ A,
                                     const float* __restrict__ W,
                                     const float* __restrict__ bias)
{
    __shared__ float As2[2][BK][2 * BM];   // duplicated A: 2 * 16KB
    __shared__ float Ws [2][BK][BN];       // 2 * 8KB

    const int bx = blockIdx.x;             // N tile (0..7)
    const int by = blockIdx.y;             // M tile (0..127)
    const int tid = threadIdx.x;
    const int tx = tid & 15;               // n sub (0..15)
    const int ty = tid >> 4;               // m sub (0..31), m = ty*4 + i

    const float* Ablk = A + (size_t)by * BM * D_IN;

    // A tile: 128 rows x 16 cols = 512 float4; 1 per thread
    const int a_row  = tid >> 2;           // 0..127
    const int a_col4 = tid & 3;
    // W tile: 16 rows x 128 cols = 512 float4; 1 per thread
    const int w_row  = tid >> 5;           // 0..15
    const int w_col4 = tid & 31;

    float4 areg, wreg;

    auto load_tile = [&](int k0) {
        areg = *reinterpret_cast<const float4*>(
            Ablk + (size_t)a_row * D_IN + k0 + a_col4 * 4);
        wreg = *reinterpret_cast<const float4*>(
            W + (size_t)(k0 + w_row) * D_OUT + (size_t)bx * BN + w_col4 * 4);
    };
    auto store_tile = [&](int s) {
        // transpose + duplicate: As2[k][2m] = As2[k][2m+1] = A[m][k]
        *reinterpret_cast<float2*>(&As2[s][a_col4 * 4 + 0][2 * a_row]) =
            make_float2(areg.x, areg.x);
        *reinterpret_cast<float2*>(&As2[s][a_col4 * 4 + 1][2 * a_row]) =
            make_float2(areg.y, areg.y);
        *reinterpret_cast<float2*>(&As2[s][a_col4 * 4 + 2][2 * a_row]) =
            make_float2(areg.z, areg.z);
        *reinterpret_cast<float2*>(&As2[s][a_col4 * 4 + 3][2 * a_row]) =
            make_float2(areg.w, areg.w);
        *reinterpret_cast<float4*>(&Ws[s][w_row][w_col4 * 4]) = wreg;
    };

    // acc2[i][j]: m = by*BM + ty*4 + i;  n = bx*BN + 32*j + 2*tx + {lo,hi}
    ull acc2[TM][4];
    ull tot2[TM][4];
    #pragma unroll
    for (int i = 0; i < TM; i++)
        #pragma unroll
        for (int j = 0; j < 4; j++)
            acc2[i][j] = 0ULL;

    load_tile(0);
    store_tile(0);
    __syncthreads();
    int cur = 0;

    for (int it = 0; it < NITER; ++it) {
        if (it + 1 < NITER) load_tile((it + 1) * BK);

        if (it == FOLD_IT) {
            // chunk boundary: save c0, restart accumulator for c1
            #pragma unroll
            for (int i = 0; i < TM; i++)
                #pragma unroll
                for (int j = 0; j < 4; j++) {
                    tot2[i][j] = acc2[i][j];
                    acc2[i][j] = 0ULL;
                }
        }

        #pragma unroll
        for (int k = 0; k < BK; k++) {
            // dup-A: 2x LDS.128 broadcast (uniform across tx)
            const ulonglong2* asrc = reinterpret_cast<const ulonglong2*>(
                &As2[cur][k][2 * (ty * TM)]);
            ull a2[TM];
            #pragma unroll
            for (int ii = 0; ii < 2; ii++) {
                ulonglong2 v = asrc[ii];
                a2[2 * ii + 0] = v.x;
                a2[2 * ii + 1] = v.y;
            }
            // W: 4x LDS.64, banks 2*tx -> conflict-free
            ull w2[4];
            #pragma unroll
            for (int j = 0; j < 4; j++)
                w2[j] = *reinterpret_cast<const ull*>(
                    &Ws[cur][k][32 * j + 2 * tx]);
            #pragma unroll
            for (int i = 0; i < TM; i++)
                #pragma unroll
                for (int j = 0; j < 4; j++)
                    acc2[i][j] = fma2(a2[i], w2[j], acc2[i][j]);
        }

        if (it + 1 < NITER) {
            store_tile(cur ^ 1);
            __syncthreads();
            cur ^= 1;
        }
    }

    // final combine: tot = c0 + c1 (one rn add per lane)
    #pragma unroll
    for (int i = 0; i < TM; i++)
        #pragma unroll
        for (int j = 0; j < 4; j++)
            tot2[i][j] = add2(tot2[i][j], acc2[i][j]);

    // Epilogue: + bias (one rn add per lane), coalesced float2 stores
    #pragma unroll
    for (int i = 0; i < TM; i++) {
        size_t row = (size_t)by * BM + ty * TM + i;
        #pragma unroll
        for (int j = 0; j < 4; j++) {
            int col = bx * BN + 32 * j + 2 * tx;
            float2 p  = unpack2(tot2[i][j]);
            float2 bv = *reinterpret_cast<const float2*>(bias + col);
            float2 o;
            o.x = __fadd_rn(p.x, bv.x);
            o.y = __fadd_rn(p.y, bv.y);
            *reinterpret_cast<float2*>(g_X + row * D_OUT + col) = o;
        }
    }
}

// ---------------------------------------------------------------------------
// Kernel 2: LIF scan, 2 lanes per thread via float2 (proven bit-exact).
// ---------------------------------------------------------------------------
__global__ __launch_bounds__(256)
void lif_scan_v2_kernel(float* __restrict__ out)
{
    int idx = blockIdx.x * blockDim.x + threadIdx.x;   // 0 .. BD/2-1
    const float2* src = reinterpret_cast<const float2*>(g_X) + idx;
    float2* dst = reinterpret_cast<float2*>(out) + idx;
    const int stride2 = BD / 2;

    float2 u = make_float2(0.f, 0.f);
    #pragma unroll 8
    for (int t = 0; t < T_STEPS; t++) {
        float2 x = src[(size_t)t * stride2];
        float2 s;
        u.x = __fadd_rn(__fmul_rn(0.75f, u.x), x.x);
        u.y = __fadd_rn(__fmul_rn(0.75f, u.y), x.y);
        s.x = (__fsub_rn(u.x, 1.0f) >= 0.0f) ? 1.0f : 0.0f;
        s.y = (__fsub_rn(u.y, 1.0f) >= 0.0f) ? 1.0f : 0.0f;
        dst[(size_t)t * stride2] = s;
        u.x = __fsub_rn(u.x, s.x);
        u.y = __fsub_rn(u.y, s.y);
    }
}

// ---------------------------------------------------------------------------
extern "C" void kernel_launch(void* const* d_in, const int* in_sizes, int n_in,
                              void* d_out, int out_size)
{
    const float* inputs = (const float*)d_in[0];   // [T, B, D_in]
    const float* W      = (const float*)d_in[1];   // [D_in, D_out]
    const float* bias   = (const float*)d_in[2];   // [D_out]
    float* out          = (float*)d_out;           // [T, B, D_out]

    dim3 gemm_grid(D_OUT / BN, M_TOT / BM);        // (8, 128)
    sgemm_bias_splitk2_f32x2_kernel<<<gemm_grid, NTHREADS>>>(inputs, W, bias);

    lif_scan_v2_kernel<<<(BD / 2) / 256, 256>>>(out);
}

// round 10
// speedup vs baseline: 1.1156x; 1.1156x over previous
#include <cuda_runtime.h>
#include <cuda_bf16.h>
#include <cstdint>

// Problem dims (fixed by the dataset)
#define T_STEPS 128
#define BATCH   128
#define D_IN    1024
#define D_OUT   1024
#define M_TOT   (T_STEPS * BATCH)   // 16384
#define BD      (BATCH * D_OUT)     // 131072

// GEMM tiling (R8-proven shape): 128x128 CTA tile, 256 threads, 8x(4x2)/thread
#define BM 128
#define BN 128
#define BK 16
#define TM 8
#define NTHREADS 256
#define NITER   (D_IN / BK)     // 64
#define FOLD_IT 32              // iteration where K=512 chunk boundary falls

// Scratch for X = A @ W + b  (64 MB) — __device__ global, no allocation.
__device__ float g_X[(size_t)M_TOT * D_OUT];

typedef unsigned long long ull;

// Packed f32x2: two independent IEEE-rn fp32 ops per instruction.
// Per-lane results are bit-identical to scalar FFMA / FADD.rn.
__device__ __forceinline__ ull fma2(ull a, ull b, ull c) {
    ull d;
    asm("fma.rn.f32x2 %0, %1, %2, %3;" : "=l"(d) : "l"(a), "l"(b), "l"(c));
    return d;
}
__device__ __forceinline__ float2 unpack2(ull v) {
    float2 f;
    asm("mov.b64 {%0, %1}, %2;" : "=f"(f.x), "=f"(f.y) : "l"(v));
    return f;
}

// ---------------------------------------------------------------------------
// Kernel 1: X[16384,1024] = A[16384,1024] @ W[1024,1024] + b
// Bit-exact split-K=2 ordering (PROVEN: rel_err == 0.0):
//   c0 = serial ascending FFMA over k=0..511
//   c1 = serial ascending FFMA over k=512..1023
//   X  = ((c0 + c1) + bias), each add separately rounded.
// This round: c0 is streamed to g_X at the fold point (same cells the
// epilogue overwrites) instead of living in 64 registers -> ~110 regs ->
// 2 CTAs/SM (4 warps/SMSP) with the R8 reuse pattern intact.
// ---------------------------------------------------------------------------
__global__ __launch_bounds__(NTHREADS, 2)
void sgemm_bias_splitk2_f32x2_kernel(const float* __restrict__ A,
                                     const float* __restrict__ W,
                                     const float* __restrict__ bias)
{
    __shared__ float As2[2][BK][2 * BM];   // duplicated A: 2 * 16KB
    __shared__ float Ws [2][BK][BN];       // 2 * 8KB

    const int bx = blockIdx.x;             // N tile (0..7)
    const int by = blockIdx.y;             // M tile (0..127)
    const int tid = threadIdx.x;
    const int tx = tid & 15;               // n sub (0..15)
    const int ty = tid >> 4;               // m sub (0..15), m = ty*8 + i

    const float* Ablk = A + (size_t)by * BM * D_IN;

    // A tile: 128 rows x 16 cols = 512 float4; 2 per thread
    const int a_row  = tid >> 2;           // 0..63 (+64)
    const int a_col4 = tid & 3;
    // W tile: 16 rows x 128 cols = 512 float4; 2 per thread
    const int w_row  = tid >> 5;           // 0..7 (+8)
    const int w_col4 = tid & 31;

    float4 areg[2], wreg[2];

    auto load_tile = [&](int k0) {
        #pragma unroll
        for (int i = 0; i < 2; i++) {
            int r = a_row + i * 64;
            areg[i] = *reinterpret_cast<const float4*>(
                Ablk + (size_t)r * D_IN + k0 + a_col4 * 4);
        }
        #pragma unroll
        for (int i = 0; i < 2; i++) {
            int r = w_row + i * 8;
            wreg[i] = *reinterpret_cast<const float4*>(
                W + (size_t)(k0 + r) * D_OUT + (size_t)bx * BN + w_col4 * 4);
        }
    };
    auto store_tile = [&](int s) {
        #pragma unroll
        for (int i = 0; i < 2; i++) {
            int r = a_row + i * 64;
            *reinterpret_cast<float2*>(&As2[s][a_col4 * 4 + 0][2 * r]) =
                make_float2(areg[i].x, areg[i].x);
            *reinterpret_cast<float2*>(&As2[s][a_col4 * 4 + 1][2 * r]) =
                make_float2(areg[i].y, areg[i].y);
            *reinterpret_cast<float2*>(&As2[s][a_col4 * 4 + 2][2 * r]) =
                make_float2(areg[i].z, areg[i].z);
            *reinterpret_cast<float2*>(&As2[s][a_col4 * 4 + 3][2 * r]) =
                make_float2(areg[i].w, areg[i].w);
        }
        #pragma unroll
        for (int i = 0; i < 2; i++) {
            int r = w_row + i * 8;
            *reinterpret_cast<float4*>(&Ws[s][r][w_col4 * 4]) = wreg[i];
        }
    };

    // acc2[i][j]: m = by*BM + ty*8 + i;  n = bx*BN + 32*j + 2*tx + {lo,hi}
    ull acc2[TM][4];
    #pragma unroll
    for (int i = 0; i < TM; i++)
        #pragma unroll
        for (int j = 0; j < 4; j++)
            acc2[i][j] = 0ULL;

    load_tile(0);
    store_tile(0);
    __syncthreads();
    int cur = 0;

    for (int it = 0; it < NITER; ++it) {
        if (it + 1 < NITER) load_tile((it + 1) * BK);

        if (it == FOLD_IT) {
            // chunk boundary: stream c0 to g_X (same cells the epilogue will
            // overwrite), then restart the accumulator for c1.
            #pragma unroll
            for (int i = 0; i < TM; i++) {
                size_t row = (size_t)by * BM + ty * TM + i;
                #pragma unroll
                for (int j = 0; j < 4; j++) {
                    int col = bx * BN + 32 * j + 2 * tx;
                    *reinterpret_cast<float2*>(g_X + row * D_OUT + col) =
                        unpack2(acc2[i][j]);
                    acc2[i][j] = 0ULL;
                }
            }
        }

        #pragma unroll
        for (int k = 0; k < BK; k++) {
            // dup-A: 4x LDS.128 broadcast (2 distinct addrs per warp)
            const ulonglong2* asrc = reinterpret_cast<const ulonglong2*>(
                &As2[cur][k][2 * (ty * TM)]);
            ull a2[TM];
            #pragma unroll
            for (int ii = 0; ii < 4; ii++) {
                ulonglong2 v = asrc[ii];
                a2[2 * ii + 0] = v.x;
                a2[2 * ii + 1] = v.y;
            }
            // W: 4x LDS.64, banks 2*tx -> conflict-free
            ull w2[4];
            #pragma unroll
            for (int j = 0; j < 4; j++)
                w2[j] = *reinterpret_cast<const ull*>(
                    &Ws[cur][k][32 * j + 2 * tx]);
            #pragma unroll
            for (int i = 0; i < TM; i++)
                #pragma unroll
                for (int j = 0; j < 4; j++)
                    acc2[i][j] = fma2(a2[i], w2[j], acc2[i][j]);
        }

        if (it + 1 < NITER) {
            store_tile(cur ^ 1);
            __syncthreads();
            cur ^= 1;
        }
    }

    // Epilogue: reload c0, tot = (c0 + c1), out = tot + bias (each add
    // separately rounded, identical ordering to the proven version).
    #pragma unroll
    for (int i = 0; i < TM; i++) {
        size_t row = (size_t)by * BM + ty * TM + i;
        #pragma unroll
        for (int j = 0; j < 4; j++) {
            int col = bx * BN + 32 * j + 2 * tx;
            float* dst = g_X + row * D_OUT + col;
            float2 c0 = *reinterpret_cast<const float2*>(dst);
            float2 c1 = unpack2(acc2[i][j]);
            float2 bv = *reinterpret_cast<const float2*>(bias + col);
            float2 o;
            o.x = __fadd_rn(__fadd_rn(c0.x, c1.x), bv.x);
            o.y = __fadd_rn(__fadd_rn(c0.y, c1.y), bv.y);
            *reinterpret_cast<float2*>(dst) = o;
        }
    }
}

// ---------------------------------------------------------------------------
// Kernel 2: LIF scan, 2 lanes per thread via float2 (proven bit-exact).
// ---------------------------------------------------------------------------
__global__ __launch_bounds__(256)
void lif_scan_v2_kernel(float* __restrict__ out)
{
    int idx = blockIdx.x * blockDim.x + threadIdx.x;   // 0 .. BD/2-1
    const float2* src = reinterpret_cast<const float2*>(g_X) + idx;
    float2* dst = reinterpret_cast<float2*>(out) + idx;
    const int stride2 = BD / 2;

    float2 u = make_float2(0.f, 0.f);
    #pragma unroll 8
    for (int t = 0; t < T_STEPS; t++) {
        float2 x = src[(size_t)t * stride2];
        float2 s;
        u.x = __fadd_rn(__fmul_rn(0.75f, u.x), x.x);
        u.y = __fadd_rn(__fmul_rn(0.75f, u.y), x.y);
        s.x = (__fsub_rn(u.x, 1.0f) >= 0.0f) ? 1.0f : 0.0f;
        s.y = (__fsub_rn(u.y, 1.0f) >= 0.0f) ? 1.0f : 0.0f;
        dst[(size_t)t * stride2] = s;
        u.x = __fsub_rn(u.x, s.x);
        u.y = __fsub_rn(u.y, s.y);
    }
}

// ---------------------------------------------------------------------------
extern "C" void kernel_launch(void* const* d_in, const int* in_sizes, int n_in,
                              void* d_out, int out_size)
{
    const float* inputs = (const float*)d_in[0];   // [T, B, D_in]
    const float* W      = (const float*)d_in[1];   // [D_in, D_out]
    const float* bias   = (const float*)d_in[2];   // [D_out]
    float* out          = (float*)d_out;           // [T, B, D_out]

    dim3 gemm_grid(D_OUT / BN, M_TOT / BM);        // (8, 128)
    sgemm_bias_splitk2_f32x2_kernel<<<gemm_grid, NTHREADS>>>(inputs, W, bias);

    lif_scan_v2_kernel<<<(BD / 2) / 256, 256>>>(out);
}